// round 9
// baseline (speedup 1.0000x reference)
#include <cuda_runtime.h>
#include <mma.h>
#include <math.h>
#include <stdint.h>

using namespace nvcuda;

#define GRIDN 16
#define NN 256
#define DD 64
#define BB 4096
#define FF 512
#define HH 16384
#define CC 1000
#define CPAD 1024

// ---------------- scratch ----------------------------------------------------
__device__ float g_nodes[(size_t)BB * HH];     // agg output of GEMM1
__device__ float g_xr[(size_t)BB * FF];        // x rounded to tf32
__device__ float g_win2[(size_t)HH * FF];      // adj-folded W_in (tf32-rounded)
__device__ float g_bin2[HH];                   // folded b_in
__device__ float g_w[(size_t)BB * CPAD];       // softmax weights (tf32-rounded)
__device__ float g_mmat[(size_t)CC * CPAD];    // folded basis x W_out (tf32-rounded)
__device__ float g_adjw[NN * 4];
__device__ int   g_adjn[NN * 4];
__device__ float g_K[4 * DD];

__device__ __forceinline__ float sigmoidf_(float x) { return 1.0f / (1.0f + expf(-x)); }
__device__ __forceinline__ float clip3(float x) { return fminf(fmaxf(x, -3.0f), 3.0f); }

// ---------------- prep: adjacency rows + K = basis @ k_w^T + k_b ------------
__global__ void prep_kernel(const float* __restrict__ adjw,
                            const float* __restrict__ k_w,
                            const float* __restrict__ k_b,
                            const float* __restrict__ basis)
{
    int t = threadIdx.x;
    int r = t >> 4, c = t & 15;
    int nb[4]; int cnt = 0;
    if (r > 0)         nb[cnt++] = t - GRIDN;
    if (r < GRIDN - 1) nb[cnt++] = t + GRIDN;
    if (c > 0)         nb[cnt++] = t - 1;
    if (c < GRIDN - 1) nb[cnt++] = t + 1;

    float w[4] = {0.f, 0.f, 0.f, 0.f};
    float deg = 0.f;
    for (int j = 0; j < cnt; j++) { w[j] = sigmoidf_(adjw[t * NN + nb[j]]); deg += w[j]; }
    deg = fmaxf(deg, 1e-6f);
    int over = 0;
    for (int j = 0; j < cnt; j++) { w[j] /= deg; if (w[j] > 0.1f) over++; }
    if (over < 1) w[0] = fmaxf(w[0], 0.5f);
    for (int j = 0; j < 4; j++) {
        g_adjw[t * 4 + j] = (j < cnt) ? w[j] : 0.f;
        g_adjn[t * 4 + j] = (j < cnt) ? nb[j] : t;
    }

    int kr = t >> 6, kc = t & 63;
    float acc = k_b[kc];
    for (int d = 0; d < DD; d++) acc += basis[kr * DD + d] * k_w[kc * DD + d];
    g_K[kr * DD + kc] = acc;
}

// ---------------- fold adjacency into W_in / b_in (tf32-round W) ------------
__global__ void fold_win_kernel(const float* __restrict__ W_in, const float* __restrict__ b_in)
{
    int idx = blockIdx.x * blockDim.x + threadIdx.x;
    if (idx >= HH * (FF / 4)) return;
    int row = idx >> 7, c4 = idx & 127;
    int n = row >> 6, d = row & 63;
    float w0 = g_adjw[n * 4 + 0], w1 = g_adjw[n * 4 + 1];
    float w2 = g_adjw[n * 4 + 2], w3 = g_adjw[n * 4 + 3];
    int   r0 = g_adjn[n * 4 + 0] * DD + d, r1 = g_adjn[n * 4 + 1] * DD + d;
    int   r2 = g_adjn[n * 4 + 2] * DD + d, r3 = g_adjn[n * 4 + 3] * DD + d;
    float4 a = ((const float4*)(W_in + (size_t)r0 * FF))[c4];
    float4 b = ((const float4*)(W_in + (size_t)r1 * FF))[c4];
    float4 c = ((const float4*)(W_in + (size_t)r2 * FF))[c4];
    float4 e = ((const float4*)(W_in + (size_t)r3 * FF))[c4];
    float4 o;
    o.x = wmma::__float_to_tf32(w0 * a.x + w1 * b.x + w2 * c.x + w3 * e.x);
    o.y = wmma::__float_to_tf32(w0 * a.y + w1 * b.y + w2 * c.y + w3 * e.y);
    o.z = wmma::__float_to_tf32(w0 * a.z + w1 * b.z + w2 * c.z + w3 * e.z);
    o.w = wmma::__float_to_tf32(w0 * a.w + w1 * b.w + w2 * c.w + w3 * e.w);
    ((float4*)(g_win2 + (size_t)row * FF))[c4] = o;
    if (c4 == 0)
        g_bin2[row] = w0 * b_in[r0] + w1 * b_in[r1] + w2 * b_in[r2] + w3 * b_in[r3];
}

// ---------------- round x to tf32 --------------------------------------------
__global__ void round_x_kernel(const float* __restrict__ x)
{
    int i = blockIdx.x * blockDim.x + threadIdx.x;
    if (i >= BB * FF / 4) return;
    float4 v = ((const float4*)x)[i];
    v.x = wmma::__float_to_tf32(v.x); v.y = wmma::__float_to_tf32(v.y);
    v.z = wmma::__float_to_tf32(v.z); v.w = wmma::__float_to_tf32(v.w);
    ((float4*)g_xr)[i] = v;
}

// ---------------- Mmat[c, n*4+j] = sum_d basis[j,d] * W_out[c, n*64+d] ------
__global__ void mmat_kernel(const float* __restrict__ W_out, const float* __restrict__ basis)
{
    int gw = (blockIdx.x * blockDim.x + threadIdx.x) >> 5;
    int lane = threadIdx.x & 31;
    if (gw >= CC * NN) return;
    const float* row = W_out + (size_t)gw * DD;
    float v0 = row[lane], v1 = row[lane + 32];
    float r0 = v0 * basis[       lane] + v1 * basis[       lane + 32];
    float r1 = v0 * basis[ 64 +  lane] + v1 * basis[ 64 +  lane + 32];
    float r2 = v0 * basis[128 +  lane] + v1 * basis[128 +  lane + 32];
    float r3 = v0 * basis[192 +  lane] + v1 * basis[192 +  lane + 32];
    #pragma unroll
    for (int o = 16; o; o >>= 1) {
        r0 += __shfl_xor_sync(0xffffffffu, r0, o);
        r1 += __shfl_xor_sync(0xffffffffu, r1, o);
        r2 += __shfl_xor_sync(0xffffffffu, r2, o);
        r3 += __shfl_xor_sync(0xffffffffu, r3, o);
    }
    if (lane == 0)
        ((float4*)g_mmat)[gw] = make_float4(
            wmma::__float_to_tf32(r0), wmma::__float_to_tf32(r1),
            wmma::__float_to_tf32(r2), wmma::__float_to_tf32(r3));
}

// ---------------- shared GEMM constants --------------------------------------
#define BK 32
#define GLDS 36

typedef wmma::fragment<wmma::matrix_a, 16, 16, 8, wmma::precision::tf32, wmma::row_major> AFrag;
typedef wmma::fragment<wmma::matrix_b, 16, 16, 8, wmma::precision::tf32, wmma::col_major> BFrag;
typedef wmma::fragment<wmma::accumulator, 16, 16, 8, float> CFrag;

// ================= GEMM1: wide tile 128x256, 512 threads ====================
#define W1_BM 128
#define W1_BN 256
#define W1_STRIDE ((W1_BM + W1_BN) * GLDS)          // 13824 floats / stage
#define W1_SMEM (3 * W1_STRIDE * 4)                  // 165888 B

__device__ __forceinline__ void w1_issue(const float* A, const float* Bw, float* sm,
                                         int t, int m0, int n0, int kt, int s)
{
    int k0 = kt * BK;
    float* dstA0 = sm + s * W1_STRIDE;
    float* dstB0 = dstA0 + W1_BM * GLDS;
    // A: 128 rows x 8 float4 = 1024; B: 256 rows x 8 float4 = 2048; 6 per thread
    #pragma unroll
    for (int i = 0; i < 2; i++) {
        int id = t + i * 512;
        int row = id >> 3, c4 = id & 7;
        const float* gA = A + (size_t)(m0 + row) * FF + k0 + c4 * 4;
        unsigned int da = (unsigned int)__cvta_generic_to_shared(dstA0 + row * GLDS + c4 * 4);
        asm volatile("cp.async.cg.shared.global [%0], [%1], 16;\n" :: "r"(da), "l"(gA));
    }
    #pragma unroll
    for (int i = 0; i < 4; i++) {
        int id = t + i * 512;
        int row = id >> 3, c4 = id & 7;
        const float* gB = Bw + (size_t)(n0 + row) * FF + k0 + c4 * 4;
        unsigned int db = (unsigned int)__cvta_generic_to_shared(dstB0 + row * GLDS + c4 * 4);
        asm volatile("cp.async.cg.shared.global [%0], [%1], 16;\n" :: "r"(db), "l"(gB));
    }
    asm volatile("cp.async.commit_group;\n" ::: "memory");
}

__global__ __launch_bounds__(512) void gemm1_wide(
    const float* __restrict__ A, const float* __restrict__ Bw, float* __restrict__ C)
{
    extern __shared__ float sm[];
    int t = threadIdx.x;
    int w = t >> 5;
    int m0 = blockIdx.y * W1_BM, n0 = blockIdx.x * W1_BN;
    int wm = w & 3, wn = w >> 2;    // 4x4 warp grid, warp tile 32x64

    CFrag acc[2][4];
    #pragma unroll
    for (int i = 0; i < 2; i++)
        #pragma unroll
        for (int j = 0; j < 4; j++) wmma::fill_fragment(acc[i][j], 0.0f);

    w1_issue(A, Bw, sm, t, m0, n0, 0, 0);
    w1_issue(A, Bw, sm, t, m0, n0, 1, 1);

    const int KT = FF / BK;   // 16
    for (int kt = 0; kt < KT; kt++) {
        if (kt == KT - 1) asm volatile("cp.async.wait_group 0;\n" ::: "memory");
        else              asm volatile("cp.async.wait_group 1;\n" ::: "memory");
        __syncthreads();
        if (kt + 2 < KT)
            w1_issue(A, Bw, sm, t, m0, n0, kt + 2, (kt + 2) % 3);

        const float* sa = sm + (kt % 3) * W1_STRIDE;
        const float* sb = sa + W1_BM * GLDS;
        #pragma unroll
        for (int kk = 0; kk < BK / 8; kk++) {
            AFrag af[2]; BFrag bf[4];
            #pragma unroll
            for (int i = 0; i < 2; i++)
                wmma::load_matrix_sync(af[i], sa + (wm * 32 + i * 16) * GLDS + kk * 8, GLDS);
            #pragma unroll
            for (int j = 0; j < 4; j++)
                wmma::load_matrix_sync(bf[j], sb + (wn * 64 + j * 16) * GLDS + kk * 8, GLDS);
            #pragma unroll
            for (int i = 0; i < 2; i++)
                #pragma unroll
                for (int j = 0; j < 4; j++)
                    wmma::mma_sync(acc[i][j], af[i], bf[j], acc[i][j]);
        }
    }

    #pragma unroll
    for (int i = 0; i < 2; i++)
        #pragma unroll
        for (int j = 0; j < 4; j++)
            wmma::store_matrix_sync(C + (size_t)(m0 + wm * 32 + i * 16) * HH + n0 + wn * 64 + j * 16,
                                    acc[i][j], HH, wmma::mem_row_major);
}

// ---------------- readout GEMM (wmma tf32, cp.async, fused bias) ------------
#define BM 128
#define BN 128
#define GSTRIDE ((BM + BN) * GLDS)
#define GEMM_SMEM (3 * GSTRIDE * 4)

__device__ __forceinline__ void g_issue(const float* A, const float* B, float* sm,
                                        int t, int m0, int n0, int K, int Nvalid,
                                        int kt, int s)
{
    int k0 = kt * BK;
    float* dstA0 = sm + s * GSTRIDE;
    float* dstB0 = dstA0 + BM * GLDS;
    #pragma unroll
    for (int i = 0; i < 4; i++) {
        int id = t + i * 256;
        int row = id >> 3, c4 = id & 7;
        const float* gA = A + (size_t)(m0 + row) * K + k0 + c4 * 4;
        unsigned int da = (unsigned int)__cvta_generic_to_shared(dstA0 + row * GLDS + c4 * 4);
        asm volatile("cp.async.cg.shared.global [%0], [%1], 16;\n" :: "r"(da), "l"(gA));
        int brow = n0 + row;
        const float* gB = B + (size_t)brow * K + k0 + c4 * 4;
        unsigned int db = (unsigned int)__cvta_generic_to_shared(dstB0 + row * GLDS + c4 * 4);
        int sz = (brow < Nvalid) ? 16 : 0;
        asm volatile("cp.async.cg.shared.global [%0], [%1], 16, %2;\n" :: "r"(db), "l"(gB), "r"(sz));
    }
    asm volatile("cp.async.commit_group;\n" ::: "memory");
}

__global__ __launch_bounds__(256, 2) void gemm_readout(
    const float* __restrict__ A, const float* __restrict__ B, float* __restrict__ C,
    int Nvalid, int K, int ldc, const float* __restrict__ bias)
{
    extern __shared__ float sm[];
    int t = threadIdx.x;
    int m0 = blockIdx.y * BM, n0 = blockIdx.x * BN;
    int w = t >> 5, wm = w & 1, wn = w >> 1;
    int KT = K / BK;

    CFrag acc[4][2];
    #pragma unroll
    for (int i = 0; i < 4; i++)
        #pragma unroll
        for (int j = 0; j < 2; j++) wmma::fill_fragment(acc[i][j], 0.0f);

    g_issue(A, B, sm, t, m0, n0, K, Nvalid, 0, 0);
    g_issue(A, B, sm, t, m0, n0, K, Nvalid, 1, 1);

    for (int kt = 0; kt < KT; kt++) {
        if (kt == KT - 1) asm volatile("cp.async.wait_group 0;\n" ::: "memory");
        else              asm volatile("cp.async.wait_group 1;\n" ::: "memory");
        __syncthreads();
        if (kt + 2 < KT)
            g_issue(A, B, sm, t, m0, n0, K, Nvalid, kt + 2, (kt + 2) % 3);

        const float* sa = sm + (kt % 3) * GSTRIDE;
        const float* sb = sa + BM * GLDS;
        #pragma unroll
        for (int kk = 0; kk < BK / 8; kk++) {
            AFrag af[4]; BFrag bf[2];
            #pragma unroll
            for (int i = 0; i < 4; i++)
                wmma::load_matrix_sync(af[i], sa + (wm * 64 + i * 16) * GLDS + kk * 8, GLDS);
            #pragma unroll
            for (int j = 0; j < 2; j++)
                wmma::load_matrix_sync(bf[j], sb + (wn * 32 + j * 16) * GLDS + kk * 8, GLDS);
            #pragma unroll
            for (int i = 0; i < 4; i++)
                #pragma unroll
                for (int j = 0; j < 2; j++)
                    wmma::mma_sync(acc[i][j], af[i], bf[j], acc[i][j]);
        }
    }

    __syncthreads();
    float* tile = sm;   // 128 x 132 staging
    #pragma unroll
    for (int i = 0; i < 4; i++)
        #pragma unroll
        for (int j = 0; j < 2; j++)
            wmma::store_matrix_sync(tile + (wm * 64 + i * 16) * 132 + wn * 32 + j * 16,
                                    acc[i][j], 132, wmma::mem_row_major);
    __syncthreads();
    for (int idx = t; idx < BM * BN; idx += 256) {
        int r = idx >> 7, c = idx & 127;
        int col = n0 + c;
        if (col < Nvalid)
            C[(size_t)(m0 + r) * ldc + col] = tile[r * 132 + c] + bias[col];
    }
}

// ---------------- fused middle (R7-proven, 512 threads / 16 warps) ----------
#define MLD 68
constexpr int MID_SMEM_FLOATS = 2 * 256 * MLD + 3 * 64 * MLD + 256 + 64 + 64;
constexpr int MID_SMEM_BYTES  = MID_SMEM_FLOATS * 4;   // ~193 KB

__global__ __launch_bounds__(512) void middle_kernel(
    const float* __restrict__ V_slow, const float* __restrict__ sem_mem,
    const float* __restrict__ mix_w, const float* __restrict__ mix_b,
    const float* __restrict__ q_w, const float* __restrict__ q_b)
{
    extern __shared__ float smem_[];
    float* sA   = smem_;               // 256*68 (y_pred, v_pred, cell_out)
    float* sB   = sA + 256 * MLD;      // 256*68 (agg, v, Q)
    float* sV   = sB + 256 * MLD;      // 64*68
    float* sS   = sV + 64 * MLD;       // 64*68
    float* sQm  = sS + 64 * MLD;       // 64*68
    float* sKb  = sQm + 64 * MLD;      // 256
    float* sqb  = sKb + 256;           // 64
    float* smw  = sqb + 64;            // 64

    int b = blockIdx.x;
    int t = threadIdx.x;
    int w = t >> 5;
    int rb = (w >> 1) * 32;            // 8 row-blocks of 32
    int cb = (w & 1) * 32;             // 2 col-blocks of 32

    for (int i = t; i < 64 * 64; i += 512) {
        int r = i >> 6, c2 = i & 63;
        sV[r * MLD + c2]  = wmma::__float_to_tf32(V_slow[i]);
        sS[r * MLD + c2]  = wmma::__float_to_tf32(sem_mem[i]);
        sQm[r * MLD + c2] = wmma::__float_to_tf32(q_w[i]);
    }
    if (t < 256) sKb[t] = g_K[t];
    if (t < 64) { sqb[t] = q_b[t]; smw[t] = mix_w[t]; }
    float mixb = mix_b[0];

    // agg (pre-folded) + bias -> sB (tf32)
    {
        const float4* np_ = (const float4*)(g_nodes + (size_t)b * HH);
        const float4* bp_ = (const float4*)g_bin2;
        for (int i = t; i < HH / 4; i += 512) {
            float4 v = np_[i], bb = bp_[i];
            int n = i >> 4, d = (i & 15) << 2;
            float* dst = &sB[n * MLD + d];
            dst[0] = wmma::__float_to_tf32(v.x + bb.x);
            dst[1] = wmma::__float_to_tf32(v.y + bb.y);
            dst[2] = wmma::__float_to_tf32(v.z + bb.z);
            dst[3] = wmma::__float_to_tf32(v.w + bb.w);
        }
    }
    __syncthreads();

    // v = clip(agg @ V^T), y_pred = clip(agg @ S^T)
    {
        CFrag vf[2][2], yf[2][2];
        #pragma unroll
        for (int i = 0; i < 2; i++)
            #pragma unroll
            for (int j = 0; j < 2; j++) { wmma::fill_fragment(vf[i][j], 0.f); wmma::fill_fragment(yf[i][j], 0.f); }
        #pragma unroll
        for (int kk = 0; kk < 8; kk++) {
            AFrag a0, a1; BFrag bv0, bv1, bs0, bs1;
            wmma::load_matrix_sync(a0, &sB[(rb     ) * MLD + kk * 8], MLD);
            wmma::load_matrix_sync(a1, &sB[(rb + 16) * MLD + kk * 8], MLD);
            wmma::load_matrix_sync(bv0, &sV[(cb     ) * MLD + kk * 8], MLD);
            wmma::load_matrix_sync(bv1, &sV[(cb + 16) * MLD + kk * 8], MLD);
            wmma::load_matrix_sync(bs0, &sS[(cb     ) * MLD + kk * 8], MLD);
            wmma::load_matrix_sync(bs1, &sS[(cb + 16) * MLD + kk * 8], MLD);
            wmma::mma_sync(vf[0][0], a0, bv0, vf[0][0]);
            wmma::mma_sync(vf[0][1], a0, bv1, vf[0][1]);
            wmma::mma_sync(vf[1][0], a1, bv0, vf[1][0]);
            wmma::mma_sync(vf[1][1], a1, bv1, vf[1][1]);
            wmma::mma_sync(yf[0][0], a0, bs0, yf[0][0]);
            wmma::mma_sync(yf[0][1], a0, bs1, yf[0][1]);
            wmma::mma_sync(yf[1][0], a1, bs0, yf[1][0]);
            wmma::mma_sync(yf[1][1], a1, bs1, yf[1][1]);
        }
        #pragma unroll
        for (int i = 0; i < 2; i++)
            #pragma unroll
            for (int j = 0; j < 2; j++) {
                #pragma unroll
                for (int e = 0; e < 8; e++) {
                    vf[i][j].x[e] = clip3(vf[i][j].x[e]);
                    yf[i][j].x[e] = clip3(yf[i][j].x[e]);
                }
                wmma::store_matrix_sync(&sA[(rb + i * 16) * MLD + cb + j * 16], yf[i][j], MLD, wmma::mem_row_major);
            }
        __syncthreads();
        #pragma unroll
        for (int i = 0; i < 2; i++)
            #pragma unroll
            for (int j = 0; j < 2; j++)
                wmma::store_matrix_sync(&sB[(rb + i * 16) * MLD + cb + j * 16], vf[i][j], MLD, wmma::mem_row_major);
    }
    __syncthreads();

    // mix = sigmoid(v . mix_w + mix_b); y_pred -> tf32 in place
    int n2 = t >> 1, dh = (t & 1) * 32;
    float m;
    {
        float acc2 = 0.f;
        const float* vp = &sB[n2 * MLD + dh];
        #pragma unroll
        for (int d = 0; d < 32; d++) acc2 += vp[d] * smw[dh + d];
        acc2 += __shfl_xor_sync(0xffffffffu, acc2, 1);
        m = sigmoidf_(acc2 + mixb);
        float* ya = &sA[n2 * MLD + dh];
        #pragma unroll
        for (int d = 0; d < 32; d++) ya[d] = wmma::__float_to_tf32(ya[d]);
    }
    __syncthreads();

    // v_pred = clip(y_pred @ V^T) -> sA
    {
        CFrag pf[2][2];
        #pragma unroll
        for (int i = 0; i < 2; i++)
            #pragma unroll
            for (int j = 0; j < 2; j++) wmma::fill_fragment(pf[i][j], 0.f);
        #pragma unroll
        for (int kk = 0; kk < 8; kk++) {
            AFrag a0, a1; BFrag bv0, bv1;
            wmma::load_matrix_sync(a0, &sA[(rb     ) * MLD + kk * 8], MLD);
            wmma::load_matrix_sync(a1, &sA[(rb + 16) * MLD + kk * 8], MLD);
            wmma::load_matrix_sync(bv0, &sV[(cb     ) * MLD + kk * 8], MLD);
            wmma::load_matrix_sync(bv1, &sV[(cb + 16) * MLD + kk * 8], MLD);
            wmma::mma_sync(pf[0][0], a0, bv0, pf[0][0]);
            wmma::mma_sync(pf[0][1], a0, bv1, pf[0][1]);
            wmma::mma_sync(pf[1][0], a1, bv0, pf[1][0]);
            wmma::mma_sync(pf[1][1], a1, bv1, pf[1][1]);
        }
        #pragma unroll
        for (int i = 0; i < 2; i++)
            #pragma unroll
            for (int j = 0; j < 2; j++)
                #pragma unroll
                for (int e = 0; e < 8; e++) pf[i][j].x[e] = clip3(pf[i][j].x[e]);
        __syncthreads();
        #pragma unroll
        for (int i = 0; i < 2; i++)
            #pragma unroll
            for (int j = 0; j < 2; j++)
                wmma::store_matrix_sync(&sA[(rb + i * 16) * MLD + cb + j * 16], pf[i][j], MLD, wmma::mem_row_major);
    }
    __syncthreads();

    // cell_out = tf32(clip(mix*v + (1-mix)*v_pred)) -> sA
    {
        const float* va = &sB[n2 * MLD + dh];
        float* pa = &sA[n2 * MLD + dh];
        #pragma unroll
        for (int d = 0; d < 32; d++)
            pa[d] = wmma::__float_to_tf32(clip3(m * va[d] + (1.f - m) * pa[d]));
    }
    __syncthreads();

    // Q = cell_out @ q_w^T -> sB
    {
        CFrag qf[2][2];
        #pragma unroll
        for (int i = 0; i < 2; i++)
            #pragma unroll
            for (int j = 0; j < 2; j++) wmma::fill_fragment(qf[i][j], 0.f);
        #pragma unroll
        for (int kk = 0; kk < 8; kk++) {
            AFrag a0, a1; BFrag bq0, bq1;
            wmma::load_matrix_sync(a0, &sA[(rb     ) * MLD + kk * 8], MLD);
            wmma::load_matrix_sync(a1, &sA[(rb + 16) * MLD + kk * 8], MLD);
            wmma::load_matrix_sync(bq0, &sQm[(cb     ) * MLD + kk * 8], MLD);
            wmma::load_matrix_sync(bq1, &sQm[(cb + 16) * MLD + kk * 8], MLD);
            wmma::mma_sync(qf[0][0], a0, bq0, qf[0][0]);
            wmma::mma_sync(qf[0][1], a0, bq1, qf[0][1]);
            wmma::mma_sync(qf[1][0], a1, bq0, qf[1][0]);
            wmma::mma_sync(qf[1][1], a1, bq1, qf[1][1]);
        }
        #pragma unroll
        for (int i = 0; i < 2; i++)
            #pragma unroll
            for (int j = 0; j < 2; j++)
                wmma::store_matrix_sync(&sB[(rb + i * 16) * MLD + cb + j * 16], qf[i][j], MLD, wmma::mem_row_major);
    }
    __syncthreads();

    // attention: 2 threads/row, 4 dots + 1-step shuffle, softmax -> g_w
    {
        float qv[32];
        #pragma unroll
        for (int d = 0; d < 32; d++) qv[d] = sB[n2 * MLD + dh + d] + sqb[dh + d];
        float s0 = 0.f, s1 = 0.f, s2 = 0.f, s3 = 0.f;
        #pragma unroll
        for (int d = 0; d < 32; d++) {
            s0 += qv[d] * sKb[dh + d];
            s1 += qv[d] * sKb[64 + dh + d];
            s2 += qv[d] * sKb[128 + dh + d];
            s3 += qv[d] * sKb[192 + dh + d];
        }
        s0 += __shfl_xor_sync(0xffffffffu, s0, 1);
        s1 += __shfl_xor_sync(0xffffffffu, s1, 1);
        s2 += __shfl_xor_sync(0xffffffffu, s2, 1);
        s3 += __shfl_xor_sync(0xffffffffu, s3, 1);
        if ((t & 1) == 0) {
            s0 *= 0.125f; s1 *= 0.125f; s2 *= 0.125f; s3 *= 0.125f;
            float mx = fmaxf(fmaxf(s0, s1), fmaxf(s2, s3));
            float e0 = expf(s0 - mx), e1 = expf(s1 - mx), e2 = expf(s2 - mx), e3 = expf(s3 - mx);
            float inv = 1.f / (e0 + e1 + e2 + e3);
            ((float4*)(g_w + (size_t)b * CPAD))[n2] = make_float4(
                wmma::__float_to_tf32(e0 * inv), wmma::__float_to_tf32(e1 * inv),
                wmma::__float_to_tf32(e2 * inv), wmma::__float_to_tf32(e3 * inv));
        }
    }
}

// ---------------- launcher ---------------------------------------------------
extern "C" void kernel_launch(void* const* d_in, const int* in_sizes, int n_in,
                              void* d_out, int out_size)
{
    (void)in_sizes; (void)n_in; (void)out_size;
    const float* x      = (const float*)d_in[0];
    const float* W_in   = (const float*)d_in[1];
    const float* b_in   = (const float*)d_in[2];
    const float* adj_w  = (const float*)d_in[3];
    const float* V_slow = (const float*)d_in[5];
    const float* sem    = (const float*)d_in[6];
    const float* mix_w  = (const float*)d_in[7];
    const float* mix_b  = (const float*)d_in[8];
    const float* basis  = (const float*)d_in[9];
    const float* q_w    = (const float*)d_in[10];
    const float* q_b    = (const float*)d_in[11];
    const float* k_w    = (const float*)d_in[12];
    const float* k_b    = (const float*)d_in[13];
    const float* W_out  = (const float*)d_in[14];
    const float* b_out  = (const float*)d_in[15];
    float* out = (float*)d_out;

    cudaFuncSetAttribute(gemm1_wide,   cudaFuncAttributeMaxDynamicSharedMemorySize, W1_SMEM);
    cudaFuncSetAttribute(gemm_readout, cudaFuncAttributeMaxDynamicSharedMemorySize, GEMM_SMEM);
    cudaFuncSetAttribute(middle_kernel, cudaFuncAttributeMaxDynamicSharedMemorySize, MID_SMEM_BYTES);

    void *p_nodes = 0, *p_w = 0, *p_mmat = 0, *p_win2 = 0, *p_xr = 0;
    cudaGetSymbolAddress(&p_nodes, g_nodes);
    cudaGetSymbolAddress(&p_w,     g_w);
    cudaGetSymbolAddress(&p_mmat,  g_mmat);
    cudaGetSymbolAddress(&p_win2,  g_win2);
    cudaGetSymbolAddress(&p_xr,    g_xr);

    prep_kernel<<<1, 256>>>(adj_w, k_w, k_b, basis);
    fold_win_kernel<<<(HH * (FF / 4) + 255) / 256, 256>>>(W_in, b_in);
    round_x_kernel<<<(BB * FF / 4 + 255) / 256, 256>>>(x);
    mmat_kernel<<<(CC * NN) / 8, 256>>>(W_out, basis);

    // agg = xr @ W_in'^T  (wide tile: 128x256, 512 threads)
    gemm1_wide<<<dim3(HH / W1_BN, BB / W1_BM), 512, W1_SMEM>>>(
        (const float*)p_xr, (const float*)p_win2, (float*)p_nodes);

    middle_kernel<<<BB, 512, MID_SMEM_BYTES>>>(V_slow, sem, mix_w, mix_b, q_w, q_b);

    // logits = w @ Mmat^T + b_out  (direct store to d_out)
    gemm_readout<<<dim3(CPAD / BN, BB / BM), 256, GEMM_SMEM>>>(
        (const float*)p_w, (const float*)p_mmat, out, CC, CPAD, CC, b_out);
}

// round 10
// speedup vs baseline: 1.0921x; 1.0921x over previous
#include <cuda_runtime.h>
#include <mma.h>
#include <math.h>
#include <stdint.h>

using namespace nvcuda;

#define GRIDN 16
#define NN 256
#define DD 64
#define BB 4096
#define FF 512
#define HH 16384
#define CC 1000
#define CPAD 1024

// ---------------- scratch ----------------------------------------------------
__device__ float g_nodes[(size_t)BB * HH];     // agg output of GEMM1
__device__ float g_xr[(size_t)BB * FF];        // x rounded to tf32
__device__ float g_win2[(size_t)HH * FF];      // adj-folded W_in (tf32-rounded)
__device__ float g_bin2[HH];                   // folded b_in
__device__ float g_w[(size_t)BB * CPAD];       // softmax weights (tf32-rounded)
__device__ float g_mmat[(size_t)CC * CPAD];    // folded basis x W_out (tf32-rounded)
__device__ float g_adjw[NN * 4];
__device__ int   g_adjn[NN * 4];
__device__ float g_K[4 * DD];

__device__ __forceinline__ float sigmoidf_(float x) { return 1.0f / (1.0f + expf(-x)); }
__device__ __forceinline__ float clip3(float x) { return fminf(fmaxf(x, -3.0f), 3.0f); }

// ---------------- prep: adjacency rows + K = basis @ k_w^T + k_b ------------
__global__ void prep_kernel(const float* __restrict__ adjw,
                            const float* __restrict__ k_w,
                            const float* __restrict__ k_b,
                            const float* __restrict__ basis)
{
    int t = threadIdx.x;
    int r = t >> 4, c = t & 15;
    int nb[4]; int cnt = 0;
    if (r > 0)         nb[cnt++] = t - GRIDN;
    if (r < GRIDN - 1) nb[cnt++] = t + GRIDN;
    if (c > 0)         nb[cnt++] = t - 1;
    if (c < GRIDN - 1) nb[cnt++] = t + 1;

    float w[4] = {0.f, 0.f, 0.f, 0.f};
    float deg = 0.f;
    for (int j = 0; j < cnt; j++) { w[j] = sigmoidf_(adjw[t * NN + nb[j]]); deg += w[j]; }
    deg = fmaxf(deg, 1e-6f);
    int over = 0;
    for (int j = 0; j < cnt; j++) { w[j] /= deg; if (w[j] > 0.1f) over++; }
    if (over < 1) w[0] = fmaxf(w[0], 0.5f);
    for (int j = 0; j < 4; j++) {
        g_adjw[t * 4 + j] = (j < cnt) ? w[j] : 0.f;
        g_adjn[t * 4 + j] = (j < cnt) ? nb[j] : t;
    }

    int kr = t >> 6, kc = t & 63;
    float acc = k_b[kc];
    for (int d = 0; d < DD; d++) acc += basis[kr * DD + d] * k_w[kc * DD + d];
    g_K[kr * DD + kc] = acc;
}

// ---------------- fold adjacency into W_in / b_in (tf32-round W) ------------
__global__ void fold_win_kernel(const float* __restrict__ W_in, const float* __restrict__ b_in)
{
    int idx = blockIdx.x * blockDim.x + threadIdx.x;
    if (idx >= HH * (FF / 4)) return;
    int row = idx >> 7, c4 = idx & 127;
    int n = row >> 6, d = row & 63;
    float w0 = g_adjw[n * 4 + 0], w1 = g_adjw[n * 4 + 1];
    float w2 = g_adjw[n * 4 + 2], w3 = g_adjw[n * 4 + 3];
    int   r0 = g_adjn[n * 4 + 0] * DD + d, r1 = g_adjn[n * 4 + 1] * DD + d;
    int   r2 = g_adjn[n * 4 + 2] * DD + d, r3 = g_adjn[n * 4 + 3] * DD + d;
    float4 a = ((const float4*)(W_in + (size_t)r0 * FF))[c4];
    float4 b = ((const float4*)(W_in + (size_t)r1 * FF))[c4];
    float4 c = ((const float4*)(W_in + (size_t)r2 * FF))[c4];
    float4 e = ((const float4*)(W_in + (size_t)r3 * FF))[c4];
    float4 o;
    o.x = wmma::__float_to_tf32(w0 * a.x + w1 * b.x + w2 * c.x + w3 * e.x);
    o.y = wmma::__float_to_tf32(w0 * a.y + w1 * b.y + w2 * c.y + w3 * e.y);
    o.z = wmma::__float_to_tf32(w0 * a.z + w1 * b.z + w2 * c.z + w3 * e.z);
    o.w = wmma::__float_to_tf32(w0 * a.w + w1 * b.w + w2 * c.w + w3 * e.w);
    ((float4*)(g_win2 + (size_t)row * FF))[c4] = o;
    if (c4 == 0)
        g_bin2[row] = w0 * b_in[r0] + w1 * b_in[r1] + w2 * b_in[r2] + w3 * b_in[r3];
}

// ---------------- round x to tf32 --------------------------------------------
__global__ void round_x_kernel(const float* __restrict__ x)
{
    int i = blockIdx.x * blockDim.x + threadIdx.x;
    if (i >= BB * FF / 4) return;
    float4 v = ((const float4*)x)[i];
    v.x = wmma::__float_to_tf32(v.x); v.y = wmma::__float_to_tf32(v.y);
    v.z = wmma::__float_to_tf32(v.z); v.w = wmma::__float_to_tf32(v.w);
    ((float4*)g_xr)[i] = v;
}

// ---------------- Mmat[c, n*4+j] = sum_d basis[j,d] * W_out[c, n*64+d] ------
__global__ void mmat_kernel(const float* __restrict__ W_out, const float* __restrict__ basis)
{
    int gw = (blockIdx.x * blockDim.x + threadIdx.x) >> 5;
    int lane = threadIdx.x & 31;
    if (gw >= CC * NN) return;
    const float* row = W_out + (size_t)gw * DD;
    float v0 = row[lane], v1 = row[lane + 32];
    float r0 = v0 * basis[       lane] + v1 * basis[       lane + 32];
    float r1 = v0 * basis[ 64 +  lane] + v1 * basis[ 64 +  lane + 32];
    float r2 = v0 * basis[128 +  lane] + v1 * basis[128 +  lane + 32];
    float r3 = v0 * basis[192 +  lane] + v1 * basis[192 +  lane + 32];
    #pragma unroll
    for (int o = 16; o; o >>= 1) {
        r0 += __shfl_xor_sync(0xffffffffu, r0, o);
        r1 += __shfl_xor_sync(0xffffffffu, r1, o);
        r2 += __shfl_xor_sync(0xffffffffu, r2, o);
        r3 += __shfl_xor_sync(0xffffffffu, r3, o);
    }
    if (lane == 0)
        ((float4*)g_mmat)[gw] = make_float4(
            wmma::__float_to_tf32(r0), wmma::__float_to_tf32(r1),
            wmma::__float_to_tf32(r2), wmma::__float_to_tf32(r3));
}

// ---------------- pipelined NT GEMM (R7-proven) -------------------------------
#define BM 128
#define BN 128
#define BK 32
#define GLDS 36
#define GSTAGE 3
#define GSTRIDE ((BM + BN) * GLDS)
#define GEMM_SMEM (GSTAGE * GSTRIDE * 4)           // 110592 B

typedef wmma::fragment<wmma::matrix_a, 16, 16, 8, wmma::precision::tf32, wmma::row_major> AFrag;
typedef wmma::fragment<wmma::matrix_b, 16, 16, 8, wmma::precision::tf32, wmma::col_major> BFrag;
typedef wmma::fragment<wmma::accumulator, 16, 16, 8, float> CFrag;

__device__ __forceinline__ void g_issue(const float* A, const float* B, float* sm,
                                        int t, int m0, int n0, int K, int Nvalid,
                                        int kt, int s)
{
    int k0 = kt * BK;
    float* dstA0 = sm + s * GSTRIDE;
    float* dstB0 = dstA0 + BM * GLDS;
    #pragma unroll
    for (int i = 0; i < 4; i++) {
        int id = t + i * 256;
        int row = id >> 3, c4 = id & 7;
        const float* gA = A + (size_t)(m0 + row) * K + k0 + c4 * 4;
        unsigned int da = (unsigned int)__cvta_generic_to_shared(dstA0 + row * GLDS + c4 * 4);
        asm volatile("cp.async.cg.shared.global [%0], [%1], 16;\n" :: "r"(da), "l"(gA));
        int brow = n0 + row;
        const float* gB = B + (size_t)brow * K + k0 + c4 * 4;
        unsigned int db = (unsigned int)__cvta_generic_to_shared(dstB0 + row * GLDS + c4 * 4);
        int sz = (brow < Nvalid) ? 16 : 0;
        asm volatile("cp.async.cg.shared.global [%0], [%1], 16, %2;\n" :: "r"(db), "l"(gB), "r"(sz));
    }
    asm volatile("cp.async.commit_group;\n" ::: "memory");
}

template<bool STORE_OUT>
__global__ __launch_bounds__(256, 2) void gemm_nt_pipe(
    const float* __restrict__ A, const float* __restrict__ B, float* __restrict__ C,
    int Nvalid, int K, int ldc, const float* __restrict__ bias)
{
    extern __shared__ float sm[];
    int t = threadIdx.x;
    int m0 = blockIdx.y * BM, n0 = blockIdx.x * BN;
    int w = t >> 5, wm = w & 1, wn = w >> 1;
    int KT = K / BK;

    CFrag acc[4][2];
    #pragma unroll
    for (int i = 0; i < 4; i++)
        #pragma unroll
        for (int j = 0; j < 2; j++) wmma::fill_fragment(acc[i][j], 0.0f);

    g_issue(A, B, sm, t, m0, n0, K, Nvalid, 0, 0);
    g_issue(A, B, sm, t, m0, n0, K, Nvalid, 1, 1);

    for (int kt = 0; kt < KT; kt++) {
        asm volatile("cp.async.wait_group 1;\n" ::: "memory");
        __syncthreads();
        if (kt + 2 < KT)
            g_issue(A, B, sm, t, m0, n0, K, Nvalid, kt + 2, (kt + 2) % GSTAGE);

        const float* sa = sm + (kt % GSTAGE) * GSTRIDE;
        const float* sb = sa + BM * GLDS;
        #pragma unroll
        for (int kk = 0; kk < BK / 8; kk++) {
            AFrag af[4]; BFrag bf[2];
            #pragma unroll
            for (int i = 0; i < 4; i++)
                wmma::load_matrix_sync(af[i], sa + (wm * 64 + i * 16) * GLDS + kk * 8, GLDS);
            #pragma unroll
            for (int j = 0; j < 2; j++)
                wmma::load_matrix_sync(bf[j], sb + (wn * 32 + j * 16) * GLDS + kk * 8, GLDS);
            #pragma unroll
            for (int i = 0; i < 4; i++)
                #pragma unroll
                for (int j = 0; j < 2; j++)
                    wmma::mma_sync(acc[i][j], af[i], bf[j], acc[i][j]);
        }
    }

    if (STORE_OUT) {
        __syncthreads();
        float* tile = sm;   // 128 x 132 staging
        #pragma unroll
        for (int i = 0; i < 4; i++)
            #pragma unroll
            for (int j = 0; j < 2; j++)
                wmma::store_matrix_sync(tile + (wm * 64 + i * 16) * 132 + wn * 32 + j * 16,
                                        acc[i][j], 132, wmma::mem_row_major);
        __syncthreads();
        for (int idx = t; idx < BM * BN; idx += 256) {
            int r = idx >> 7, c = idx & 127;
            int col = n0 + c;
            if (col < Nvalid)
                C[(size_t)(m0 + r) * ldc + col] = tile[r * 132 + c] + bias[col];
        }
    } else {
        #pragma unroll
        for (int i = 0; i < 4; i++)
            #pragma unroll
            for (int j = 0; j < 2; j++)
                wmma::store_matrix_sync(C + (size_t)(m0 + wm * 64 + i * 16) * ldc + n0 + wn * 32 + j * 16,
                                        acc[i][j], ldc, wmma::mem_row_major);
    }
}

// ---------------- persistent middle (R7 phases, prefetch + weights-once) -----
#define MLD 68
#define MID_GRID 148
constexpr int MID_SMEM_FLOATS = 2 * 256 * MLD + 3 * 64 * MLD + 256 + 64 + 64;
constexpr int MID_SMEM_BYTES  = MID_SMEM_FLOATS * 4;   // ~193 KB, 1 CTA/SM, 16 warps

__global__ __launch_bounds__(512) void middle_kernel(
    const float* __restrict__ V_slow, const float* __restrict__ sem_mem,
    const float* __restrict__ mix_w, const float* __restrict__ mix_b,
    const float* __restrict__ q_w, const float* __restrict__ q_b)
{
    extern __shared__ float smem_[];
    float* sA   = smem_;               // 256*68 (y_pred, v_pred, cell_out)
    float* sB   = sA + 256 * MLD;      // 256*68 (agg, v, Q)
    float* sV   = sB + 256 * MLD;      // 64*68
    float* sS   = sV + 64 * MLD;       // 64*68
    float* sQm  = sS + 64 * MLD;       // 64*68
    float* sKb  = sQm + 64 * MLD;      // 256
    float* sqb  = sKb + 256;           // 64
    float* smw  = sqb + 64;            // 64

    int t = threadIdx.x;
    int w = t >> 5;
    int rb = (w >> 1) * 32;            // 8 row-blocks of 32
    int cb = (w & 1) * 32;             // 2 col-blocks of 32
    int n2 = t >> 1, dh = (t & 1) * 32;

    // weights once per CTA
    for (int i = t; i < 64 * 64; i += 512) {
        int r = i >> 6, c2 = i & 63;
        sV[r * MLD + c2]  = wmma::__float_to_tf32(V_slow[i]);
        sS[r * MLD + c2]  = wmma::__float_to_tf32(sem_mem[i]);
        sQm[r * MLD + c2] = wmma::__float_to_tf32(q_w[i]);
    }
    if (t < 256) sKb[t] = g_K[t];
    if (t < 64) { sqb[t] = q_b[t]; smw[t] = mix_w[t]; }
    float mixb = mix_b[0];

    const float4* bp_ = (const float4*)g_bin2;

    // prefetch first batch
    int b = blockIdx.x;
    float4 pre[8];
    {
        const float4* np_ = (const float4*)(g_nodes + (size_t)b * HH);
        #pragma unroll
        for (int j = 0; j < 8; j++) pre[j] = np_[t + j * 512];
    }

    while (b < BB) {
        int nb = b + MID_GRID;
        __syncthreads();   // prev iteration fully consumed (incl. weight init on iter 0)

        // agg + bias -> sB (tf32)
        #pragma unroll
        for (int j = 0; j < 8; j++) {
            int i = t + j * 512;
            float4 v = pre[j], bbv = bp_[i];
            int n = i >> 4, d = (i & 15) << 2;
            float* dst = &sB[n * MLD + d];
            dst[0] = wmma::__float_to_tf32(v.x + bbv.x);
            dst[1] = wmma::__float_to_tf32(v.y + bbv.y);
            dst[2] = wmma::__float_to_tf32(v.z + bbv.z);
            dst[3] = wmma::__float_to_tf32(v.w + bbv.w);
        }
        __syncthreads();

        // v = clip(agg @ V^T), y_pred = clip(agg @ S^T)
        {
            CFrag vf[2][2], yf[2][2];
            #pragma unroll
            for (int i = 0; i < 2; i++)
                #pragma unroll
                for (int j = 0; j < 2; j++) { wmma::fill_fragment(vf[i][j], 0.f); wmma::fill_fragment(yf[i][j], 0.f); }
            #pragma unroll
            for (int kk = 0; kk < 8; kk++) {
                AFrag a0, a1; BFrag bv0, bv1, bs0, bs1;
                wmma::load_matrix_sync(a0, &sB[(rb     ) * MLD + kk * 8], MLD);
                wmma::load_matrix_sync(a1, &sB[(rb + 16) * MLD + kk * 8], MLD);
                wmma::load_matrix_sync(bv0, &sV[(cb     ) * MLD + kk * 8], MLD);
                wmma::load_matrix_sync(bv1, &sV[(cb + 16) * MLD + kk * 8], MLD);
                wmma::load_matrix_sync(bs0, &sS[(cb     ) * MLD + kk * 8], MLD);
                wmma::load_matrix_sync(bs1, &sS[(cb + 16) * MLD + kk * 8], MLD);
                wmma::mma_sync(vf[0][0], a0, bv0, vf[0][0]);
                wmma::mma_sync(vf[0][1], a0, bv1, vf[0][1]);
                wmma::mma_sync(vf[1][0], a1, bv0, vf[1][0]);
                wmma::mma_sync(vf[1][1], a1, bv1, vf[1][1]);
                wmma::mma_sync(yf[0][0], a0, bs0, yf[0][0]);
                wmma::mma_sync(yf[0][1], a0, bs1, yf[0][1]);
                wmma::mma_sync(yf[1][0], a1, bs0, yf[1][0]);
                wmma::mma_sync(yf[1][1], a1, bs1, yf[1][1]);
            }
            #pragma unroll
            for (int i = 0; i < 2; i++)
                #pragma unroll
                for (int j = 0; j < 2; j++) {
                    #pragma unroll
                    for (int e = 0; e < 8; e++) {
                        vf[i][j].x[e] = clip3(vf[i][j].x[e]);
                        yf[i][j].x[e] = clip3(yf[i][j].x[e]);
                    }
                    wmma::store_matrix_sync(&sA[(rb + i * 16) * MLD + cb + j * 16], yf[i][j], MLD, wmma::mem_row_major);
                }
            __syncthreads();
            #pragma unroll
            for (int i = 0; i < 2; i++)
                #pragma unroll
                for (int j = 0; j < 2; j++)
                    wmma::store_matrix_sync(&sB[(rb + i * 16) * MLD + cb + j * 16], vf[i][j], MLD, wmma::mem_row_major);
        }
        __syncthreads();

        // mix = sigmoid(v . mix_w + mix_b); y_pred -> tf32 in place
        float m;
        {
            float acc2 = 0.f;
            const float* vp = &sB[n2 * MLD + dh];
            #pragma unroll
            for (int d = 0; d < 32; d++) acc2 += vp[d] * smw[dh + d];
            acc2 += __shfl_xor_sync(0xffffffffu, acc2, 1);
            m = sigmoidf_(acc2 + mixb);
            float* ya = &sA[n2 * MLD + dh];
            #pragma unroll
            for (int d = 0; d < 32; d++) ya[d] = wmma::__float_to_tf32(ya[d]);
        }
        __syncthreads();

        // v_pred = clip(y_pred @ V^T) -> sA
        {
            CFrag pf[2][2];
            #pragma unroll
            for (int i = 0; i < 2; i++)
                #pragma unroll
                for (int j = 0; j < 2; j++) wmma::fill_fragment(pf[i][j], 0.f);
            #pragma unroll
            for (int kk = 0; kk < 8; kk++) {
                AFrag a0, a1; BFrag bv0, bv1;
                wmma::load_matrix_sync(a0, &sA[(rb     ) * MLD + kk * 8], MLD);
                wmma::load_matrix_sync(a1, &sA[(rb + 16) * MLD + kk * 8], MLD);
                wmma::load_matrix_sync(bv0, &sV[(cb     ) * MLD + kk * 8], MLD);
                wmma::load_matrix_sync(bv1, &sV[(cb + 16) * MLD + kk * 8], MLD);
                wmma::mma_sync(pf[0][0], a0, bv0, pf[0][0]);
                wmma::mma_sync(pf[0][1], a0, bv1, pf[0][1]);
                wmma::mma_sync(pf[1][0], a1, bv0, pf[1][0]);
                wmma::mma_sync(pf[1][1], a1, bv1, pf[1][1]);
            }
            #pragma unroll
            for (int i = 0; i < 2; i++)
                #pragma unroll
                for (int j = 0; j < 2; j++)
                    #pragma unroll
                    for (int e = 0; e < 8; e++) pf[i][j].x[e] = clip3(pf[i][j].x[e]);
            __syncthreads();
            #pragma unroll
            for (int i = 0; i < 2; i++)
                #pragma unroll
                for (int j = 0; j < 2; j++)
                    wmma::store_matrix_sync(&sA[(rb + i * 16) * MLD + cb + j * 16], pf[i][j], MLD, wmma::mem_row_major);
        }
        __syncthreads();

        // cell_out = tf32(clip(mix*v + (1-mix)*v_pred)) -> sA
        {
            const float* va = &sB[n2 * MLD + dh];
            float* pa = &sA[n2 * MLD + dh];
            #pragma unroll
            for (int d = 0; d < 32; d++)
                pa[d] = wmma::__float_to_tf32(clip3(m * va[d] + (1.f - m) * pa[d]));
        }
        __syncthreads();

        // Q = cell_out @ q_w^T -> sB
        {
            CFrag qf[2][2];
            #pragma unroll
            for (int i = 0; i < 2; i++)
                #pragma unroll
                for (int j = 0; j < 2; j++) wmma::fill_fragment(qf[i][j], 0.f);
            #pragma unroll
            for (int kk = 0; kk < 8; kk++) {
                AFrag a0, a1; BFrag bq0, bq1;
                wmma::load_matrix_sync(a0, &sA[(rb     ) * MLD + kk * 8], MLD);
                wmma::load_matrix_sync(a1, &sA[(rb + 16) * MLD + kk * 8], MLD);
                wmma::load_matrix_sync(bq0, &sQm[(cb     ) * MLD + kk * 8], MLD);
                wmma::load_matrix_sync(bq1, &sQm[(cb + 16) * MLD + kk * 8], MLD);
                wmma::mma_sync(qf[0][0], a0, bq0, qf[0][0]);
                wmma::mma_sync(qf[0][1], a0, bq1, qf[0][1]);
                wmma::mma_sync(qf[1][0], a1, bq0, qf[1][0]);
                wmma::mma_sync(qf[1][1], a1, bq1, qf[1][1]);
            }
            #pragma unroll
            for (int i = 0; i < 2; i++)
                #pragma unroll
                for (int j = 0; j < 2; j++)
                    wmma::store_matrix_sync(&sB[(rb + i * 16) * MLD + cb + j * 16], qf[i][j], MLD, wmma::mem_row_major);
        }
        __syncthreads();

        // prefetch next batch (hidden under attention + loop-top)
        if (nb < BB) {
            const float4* np_ = (const float4*)(g_nodes + (size_t)nb * HH);
            #pragma unroll
            for (int j = 0; j < 8; j++) pre[j] = np_[t + j * 512];
        }

        // attention: 2 threads/row, 4 dots + 1-step shuffle, softmax -> g_w
        {
            float qv[32];
            #pragma unroll
            for (int d = 0; d < 32; d++) qv[d] = sB[n2 * MLD + dh + d] + sqb[dh + d];
            float s0 = 0.f, s1 = 0.f, s2 = 0.f, s3 = 0.f;
            #pragma unroll
            for (int d = 0; d < 32; d++) {
                s0 += qv[d] * sKb[dh + d];
                s1 += qv[d] * sKb[64 + dh + d];
                s2 += qv[d] * sKb[128 + dh + d];
                s3 += qv[d] * sKb[192 + dh + d];
            }
            s0 += __shfl_xor_sync(0xffffffffu, s0, 1);
            s1 += __shfl_xor_sync(0xffffffffu, s1, 1);
            s2 += __shfl_xor_sync(0xffffffffu, s2, 1);
            s3 += __shfl_xor_sync(0xffffffffu, s3, 1);
            if ((t & 1) == 0) {
                s0 *= 0.125f; s1 *= 0.125f; s2 *= 0.125f; s3 *= 0.125f;
                float mx = fmaxf(fmaxf(s0, s1), fmaxf(s2, s3));
                float e0 = expf(s0 - mx), e1 = expf(s1 - mx), e2 = expf(s2 - mx), e3 = expf(s3 - mx);
                float inv = 1.f / (e0 + e1 + e2 + e3);
                ((float4*)(g_w + (size_t)b * CPAD))[n2] = make_float4(
                    wmma::__float_to_tf32(e0 * inv), wmma::__float_to_tf32(e1 * inv),
                    wmma::__float_to_tf32(e2 * inv), wmma::__float_to_tf32(e3 * inv));
            }
        }

        b = nb;
    }
}

// ---------------- launcher ---------------------------------------------------
extern "C" void kernel_launch(void* const* d_in, const int* in_sizes, int n_in,
                              void* d_out, int out_size)
{
    (void)in_sizes; (void)n_in; (void)out_size;
    const float* x      = (const float*)d_in[0];
    const float* W_in   = (const float*)d_in[1];
    const float* b_in   = (const float*)d_in[2];
    const float* adj_w  = (const float*)d_in[3];
    const float* V_slow = (const float*)d_in[5];
    const float* sem    = (const float*)d_in[6];
    const float* mix_w  = (const float*)d_in[7];
    const float* mix_b  = (const float*)d_in[8];
    const float* basis  = (const float*)d_in[9];
    const float* q_w    = (const float*)d_in[10];
    const float* q_b    = (const float*)d_in[11];
    const float* k_w    = (const float*)d_in[12];
    const float* k_b    = (const float*)d_in[13];
    const float* W_out  = (const float*)d_in[14];
    const float* b_out  = (const float*)d_in[15];
    float* out = (float*)d_out;

    cudaFuncSetAttribute(gemm_nt_pipe<false>, cudaFuncAttributeMaxDynamicSharedMemorySize, GEMM_SMEM);
    cudaFuncSetAttribute(gemm_nt_pipe<true>,  cudaFuncAttributeMaxDynamicSharedMemorySize, GEMM_SMEM);
    cudaFuncSetAttribute(middle_kernel, cudaFuncAttributeMaxDynamicSharedMemorySize, MID_SMEM_BYTES);

    void *p_nodes = 0, *p_w = 0, *p_mmat = 0, *p_win2 = 0, *p_xr = 0;
    cudaGetSymbolAddress(&p_nodes, g_nodes);
    cudaGetSymbolAddress(&p_w,     g_w);
    cudaGetSymbolAddress(&p_mmat,  g_mmat);
    cudaGetSymbolAddress(&p_win2,  g_win2);
    cudaGetSymbolAddress(&p_xr,    g_xr);

    prep_kernel<<<1, 256>>>(adj_w, k_w, k_b, basis);
    fold_win_kernel<<<(HH * (FF / 4) + 255) / 256, 256>>>(W_in, b_in);
    round_x_kernel<<<(BB * FF / 4 + 255) / 256, 256>>>(x);
    mmat_kernel<<<(CC * NN) / 8, 256>>>(W_out, basis);

    // agg = xr @ W_in'^T  (R7-proven shape)
    gemm_nt_pipe<false><<<dim3(HH / BN, BB / BM), 256, GEMM_SMEM>>>(
        (const float*)p_xr, (const float*)p_win2, (float*)p_nodes, HH, FF, HH, nullptr);

    // persistent middle
    middle_kernel<<<MID_GRID, 512, MID_SMEM_BYTES>>>(V_slow, sem, mix_w, mix_b, q_w, q_b);

    // logits = w @ Mmat^T + b_out  (direct store to d_out)
    gemm_nt_pipe<true><<<dim3(CPAD / BN, BB / BM), 256, GEMM_SMEM>>>(
        (const float*)p_w, (const float*)p_mmat, out, CC, CPAD, CC, b_out);
}